// round 1
// baseline (speedup 1.0000x reference)
#include <cuda_runtime.h>
#include <math.h>

// Shapes are fixed by the problem: B=2, L=S=2048, H=8, E=D=32.
namespace {
constexpr int B_ = 2, L_ = 2048, S_ = 2048, H_ = 8, E_ = 32, D_ = 32;
constexpr int BM = 64, BN = 64, PT = 68;   // PT: smem pitch (floats) to avoid bank conflicts
constexpr int NTHREADS = 256;
constexpr float INV = 0.17677669529663687f;                  // 1/sqrt(32) (= scale and pre-scale)
constexpr float NEG_MASK = -4294967295.0f * 0.17677669529663687f; // scale * (-(2^32-1))
constexpr int SMEM_FLOATS = 4 * E_ * PT + BN * D_ + BM * PT + 5 * BM;
constexpr int SMEM_BYTES = SMEM_FLOATS * 4;
}

__global__ __launch_bounds__(NTHREADS, 2)
void gauss_attn(const float* __restrict__ Q, const float* __restrict__ K,
                const float* __restrict__ V, float* __restrict__ O)
{
    extern __shared__ float sm[];
    float* sQt  = sm;                 // [E][PT]  transposed, scaled by INV
    float* sQgt = sQt  + E_ * PT;     // [E][PT]  gaussian-view Q rows, transposed
    float* sKt  = sQgt + E_ * PT;     // [E][PT]
    float* sKgt = sKt  + E_ * PT;     // [E][PT]
    float* sV   = sKgt + E_ * PT;     // [BN][D]
    float* sP   = sV   + BN * D_;     // [BM][PT] probabilities
    float* sQn  = sP   + BM * PT;     // [BM] |qg|^2
    float* sKn  = sQn  + BM;          // [BN] |kg|^2
    float* sM   = sKn  + BN;          // [BM] running max
    float* sSum = sM   + BM;          // [BM] running sum
    float* sAl  = sSum + BM;          // [BM] alpha for this tile

    const int b  = blockIdx.y / H_;
    const int h  = blockIdx.y % H_;
    // reversed so the heaviest l-tiles (most causal s-tiles) launch first
    const int l0 = (gridDim.x - 1 - blockIdx.x) * BM;

    const int tid = threadIdx.x;
    const int tx  = tid & 15;   // s-column group (4 cols each)
    const int ty  = tid >> 4;   // l-row group    (4 rows each)

    // ---- load Q tiles (transposed), init stats ----
    // q[b,l,h,e]  flat: ((b*L + l)*H + h)*E + e
    // qg row l    flat: (b*L*H + h*L + l)*E + e   (pure-reshape view of the same buffer)
    const float* Qb  = Q + ((size_t)(b * L_ + l0) * H_ + h) * E_;
    const float* Qgb = Q + ((size_t)b * L_ * H_ + (size_t)h * L_ + l0) * E_;
    for (int idx = tid; idx < BM * 8; idx += NTHREADS) {
        int r = idx >> 3, e4 = idx & 7, c = e4 * 4;
        float4 a = *reinterpret_cast<const float4*>(Qb  + (size_t)r * H_ * E_ + c);
        float4 g = *reinterpret_cast<const float4*>(Qgb + r * E_ + c);
        sQt [(c + 0) * PT + r] = a.x * INV; sQt [(c + 1) * PT + r] = a.y * INV;
        sQt [(c + 2) * PT + r] = a.z * INV; sQt [(c + 3) * PT + r] = a.w * INV;
        sQgt[(c + 0) * PT + r] = g.x * INV; sQgt[(c + 1) * PT + r] = g.y * INV;
        sQgt[(c + 2) * PT + r] = g.z * INV; sQgt[(c + 3) * PT + r] = g.w * INV;
    }
    if (tid < BM) {
        const float* row = Qgb + tid * E_;
        float s = 0.f;
        #pragma unroll
        for (int e = 0; e < E_; e++) { float v = row[e] * INV; s = fmaf(v, v, s); }
        sQn[tid]  = s;
        sM[tid]   = -INFINITY;
        sSum[tid] = 0.f;
    }

    float acc[8];
    #pragma unroll
    for (int i = 0; i < 8; i++) acc[i] = 0.f;

    const int r_pv = tid >> 2;          // output row this thread owns
    const int d0   = (tid & 3) * 8;     // output d-chunk

    const int ntiles = l0 / BN + 1;     // causal: s-tiles 0..l0/BN inclusive
    for (int t = 0; t < ntiles; t++) {
        const int s0 = t * BN;
        __syncthreads();  // previous P·V readers done before we overwrite K/V/P

        // ---- load K/Kg/V tile ----
        const float* Kb  = K + ((size_t)(b * S_ + s0) * H_ + h) * E_;
        const float* Kgb = K + ((size_t)b * S_ * H_ + (size_t)h * S_ + s0) * E_;
        const float* Vb  = V + ((size_t)(b * S_ + s0) * H_ + h) * D_;
        for (int idx = tid; idx < BN * 8; idx += NTHREADS) {
            int r = idx >> 3, e4 = idx & 7, c = e4 * 4;
            float4 a  = *reinterpret_cast<const float4*>(Kb  + (size_t)r * H_ * E_ + c);
            float4 g  = *reinterpret_cast<const float4*>(Kgb + r * E_ + c);
            float4 vv = *reinterpret_cast<const float4*>(Vb  + (size_t)r * H_ * D_ + c);
            sKt [(c + 0) * PT + r] = a.x * INV; sKt [(c + 1) * PT + r] = a.y * INV;
            sKt [(c + 2) * PT + r] = a.z * INV; sKt [(c + 3) * PT + r] = a.w * INV;
            sKgt[(c + 0) * PT + r] = g.x * INV; sKgt[(c + 1) * PT + r] = g.y * INV;
            sKgt[(c + 2) * PT + r] = g.z * INV; sKgt[(c + 3) * PT + r] = g.w * INV;
            reinterpret_cast<float4*>(sV + r * D_)[e4] = vv;
        }
        if (tid < BN) {
            const float* row = Kgb + tid * E_;
            float s = 0.f;
            #pragma unroll
            for (int e = 0; e < E_; e++) { float v = row[e] * INV; s = fmaf(v, v, s); }
            sKn[tid] = s;
        }
        __syncthreads();

        // ---- 64x64 scores: each thread a 4x4 micro-tile, two dot products ----
        float dt[16], cr[16];
        #pragma unroll
        for (int i = 0; i < 16; i++) { dt[i] = 0.f; cr[i] = 0.f; }

        #pragma unroll
        for (int e = 0; e < E_; e++) {
            const float4 qa = *reinterpret_cast<const float4*>(sQt  + e * PT + ty * 4);
            const float4 ka = *reinterpret_cast<const float4*>(sKt  + e * PT + tx * 4);
            const float4 qg = *reinterpret_cast<const float4*>(sQgt + e * PT + ty * 4);
            const float4 kg = *reinterpret_cast<const float4*>(sKgt + e * PT + tx * 4);
            const float qv[4] = {qa.x, qa.y, qa.z, qa.w};
            const float kv[4] = {ka.x, ka.y, ka.z, ka.w};
            const float gv[4] = {qg.x, qg.y, qg.z, qg.w};
            const float jv[4] = {kg.x, kg.y, kg.z, kg.w};
            #pragma unroll
            for (int i = 0; i < 4; i++)
                #pragma unroll
                for (int j = 0; j < 4; j++) {
                    dt[i * 4 + j] = fmaf(qv[i], kv[j], dt[i * 4 + j]);
                    cr[i * 4 + j] = fmaf(gv[i], jv[j], cr[i * 4 + j]);
                }
        }

        float qn[4], kn[4];
        #pragma unroll
        for (int i = 0; i < 4; i++) qn[i] = sQn[ty * 4 + i];
        #pragma unroll
        for (int j = 0; j < 4; j++) kn[j] = sKn[tx * 4 + j];

        // z = scale * (qk * exp(-max(|qg|^2+|kg|^2-2c, 0))), masked -> scale*NEG_INF
        #pragma unroll
        for (int i = 0; i < 4; i++) {
            const int li = l0 + ty * 4 + i;
            #pragma unroll
            for (int j = 0; j < 4; j++) {
                const int si = s0 + tx * 4 + j;
                float sq = fmaxf(qn[i] + kn[j] - 2.f * cr[i * 4 + j], 0.f);
                float zz = INV * dt[i * 4 + j] * __expf(-sq);
                dt[i * 4 + j] = (si > li) ? NEG_MASK : zz;   // reuse dt as z
            }
        }

        // ---- online-softmax row update (16-lane shfl reductions) ----
        #pragma unroll
        for (int i = 0; i < 4; i++) {
            const int row = ty * 4 + i;
            float m = fmaxf(fmaxf(dt[i*4+0], dt[i*4+1]), fmaxf(dt[i*4+2], dt[i*4+3]));
            m = fmaxf(m, __shfl_xor_sync(0xffffffffu, m, 1));
            m = fmaxf(m, __shfl_xor_sync(0xffffffffu, m, 2));
            m = fmaxf(m, __shfl_xor_sync(0xffffffffu, m, 4));
            m = fmaxf(m, __shfl_xor_sync(0xffffffffu, m, 8));
            const float mold = sM[row];
            const float mn   = fmaxf(mold, m);
            float4 p;
            p.x = __expf(dt[i*4+0] - mn);
            p.y = __expf(dt[i*4+1] - mn);
            p.z = __expf(dt[i*4+2] - mn);
            p.w = __expf(dt[i*4+3] - mn);
            *reinterpret_cast<float4*>(sP + row * PT + tx * 4) = p;
            float rs = (p.x + p.y) + (p.z + p.w);
            rs += __shfl_xor_sync(0xffffffffu, rs, 1);
            rs += __shfl_xor_sync(0xffffffffu, rs, 2);
            rs += __shfl_xor_sync(0xffffffffu, rs, 4);
            rs += __shfl_xor_sync(0xffffffffu, rs, 8);
            if (tx == 0) {
                const float al = __expf(mold - mn);   // exp(-inf)=0 on first tile
                sAl[row]  = al;
                sM[row]   = mn;
                sSum[row] = sSum[row] * al + rs;
            }
        }
        __syncthreads();

        // ---- O = O*alpha + P·V ----
        const float al = sAl[r_pv];
        #pragma unroll
        for (int d = 0; d < 8; d++) acc[d] *= al;
        #pragma unroll
        for (int s4 = 0; s4 < BN; s4 += 4) {
            const float4 p = *reinterpret_cast<const float4*>(sP + r_pv * PT + s4);
            const float pv[4] = {p.x, p.y, p.z, p.w};
            #pragma unroll
            for (int k = 0; k < 4; k++) {
                const float4 va = *reinterpret_cast<const float4*>(sV + (s4 + k) * D_ + d0);
                const float4 vb = *reinterpret_cast<const float4*>(sV + (s4 + k) * D_ + d0 + 4);
                acc[0] = fmaf(pv[k], va.x, acc[0]);
                acc[1] = fmaf(pv[k], va.y, acc[1]);
                acc[2] = fmaf(pv[k], va.z, acc[2]);
                acc[3] = fmaf(pv[k], va.w, acc[3]);
                acc[4] = fmaf(pv[k], vb.x, acc[4]);
                acc[5] = fmaf(pv[k], vb.y, acc[5]);
                acc[6] = fmaf(pv[k], vb.z, acc[6]);
                acc[7] = fmaf(pv[k], vb.w, acc[7]);
            }
        }
    }

    // ---- finalize: O /= sum; out[b, l, h, d] ----
    const float isum = 1.f / sSum[r_pv];
    float4 o0, o1;
    o0.x = acc[0] * isum; o0.y = acc[1] * isum; o0.z = acc[2] * isum; o0.w = acc[3] * isum;
    o1.x = acc[4] * isum; o1.y = acc[5] * isum; o1.z = acc[6] * isum; o1.w = acc[7] * isum;
    float* Ob = O + ((size_t)(b * L_ + l0 + r_pv) * H_ + h) * D_ + d0;
    *reinterpret_cast<float4*>(Ob)     = o0;
    *reinterpret_cast<float4*>(Ob + 4) = o1;
}

extern "C" void kernel_launch(void* const* d_in, const int* in_sizes, int n_in,
                              void* d_out, int out_size) {
    const float* Q = (const float*)d_in[0];
    const float* K = (const float*)d_in[1];
    const float* V = (const float*)d_in[2];
    float* O = (float*)d_out;

    // > 48KB dynamic smem needs the attribute; idempotent host call, capture-safe.
    cudaFuncSetAttribute(gauss_attn, cudaFuncAttributeMaxDynamicSharedMemorySize, SMEM_BYTES);

    dim3 grid(L_ / BM, B_ * H_);
    gauss_attn<<<grid, NTHREADS, SMEM_BYTES>>>(Q, K, V, O);
}